// round 3
// baseline (speedup 1.0000x reference)
#include <cuda_runtime.h>
#include <cuda_bf16.h>

// Problem constants (fixed by the reference)
#define NN      100000      // nodes
#define FF      32          // feats
#define CC      16          // classes
#define EE      1600000     // edges
#define EMB_DIM 6
#define HID     9
#define DEPTH   10
#define DIFF    0.9f

#define NF (NN * FF)

// ---------------- device scratch (no allocs allowed) ----------------
__device__ int   g_cnt[NN];
__device__ int   g_cur[NN];
__device__ int   g_rowptr[NN + 1];
__device__ int   g_col[EE];
__device__ float g_invdeg[NN];
__device__ float g_isd[NN];   // rsqrt(max(deg,1))
__device__ float g_sqd[NN];   // sqrt(max(deg,1))
__device__ float g_u0[NF];
__device__ float g_ua[NF];
__device__ float g_ub[NF];

// buffer selector: 0 -> g_u0, 1 -> g_ua, 2 -> g_ub (resolved in device code)
__device__ __forceinline__ float* buf(int sel) {
    return (sel == 0) ? g_u0 : (sel == 1) ? g_ua : g_ub;
}

// ---------------- kernels ----------------

__global__ void k_zero() {
    int i = blockIdx.x * blockDim.x + threadIdx.x;
    if (i < NN) { g_cnt[i] = 0; g_cur[i] = 0; }
}

__global__ void k_count(const int* __restrict__ edges) {
    int e = blockIdx.x * blockDim.x + threadIdx.x;
    if (e < EE) {
        int d = edges[EE + e];
        if ((unsigned)d < (unsigned)NN)
            atomicAdd(&g_cnt[d], 1);
    }
}

// single-block exclusive scan of g_cnt -> g_rowptr (N=100000, 1024 threads)
__global__ void k_scan() {
    const int T = 1024;
    int tid = threadIdx.x;
    int chunk = (NN + T - 1) / T;                 // 98
    int beg = tid * chunk;
    int end = beg + chunk; if (end > NN) end = NN;
    if (beg > NN) beg = NN;

    int sum = 0;
    for (int i = beg; i < end; i++) sum += g_cnt[i];

    __shared__ int sh[T];
    sh[tid] = sum;
    __syncthreads();
    // Hillis-Steele inclusive scan
    for (int off = 1; off < T; off <<= 1) {
        int v = (tid >= off) ? sh[tid - off] : 0;
        __syncthreads();
        sh[tid] += v;
        __syncthreads();
    }
    int run = (tid == 0) ? 0 : sh[tid - 1];       // exclusive prefix
    for (int i = beg; i < end; i++) {
        g_rowptr[i] = run;
        run += g_cnt[i];
    }
    if (tid == T - 1) g_rowptr[NN] = run;         // == EE
}

// per-node scalars + u0 = x * rsqrt(deg)
__global__ void k_prep(const float* __restrict__ x) {
    int idx = blockIdx.x * blockDim.x + threadIdx.x;
    if (idx >= NF) return;
    int n = idx >> 5;
    int c = g_cnt[n];
    float d   = (c > 0) ? (float)c : 1.0f;
    float isd = rsqrtf(d);
    g_u0[idx] = x[idx] * isd;
    if ((idx & 31) == 0) {
        g_invdeg[n] = 1.0f / d;
        g_isd[n]    = isd;
        g_sqd[n]    = sqrtf(d);
    }
}

__global__ void k_fill(const int* __restrict__ edges) {
    int e = blockIdx.x * blockDim.x + threadIdx.x;
    if (e < EE) {
        int s = edges[e];
        int d = edges[EE + e];
        if ((unsigned)d < (unsigned)NN && (unsigned)s < (unsigned)NN) {
            int pos = g_rowptr[d] + atomicAdd(&g_cur[d], 1);
            g_col[pos] = s;
        }
    }
}

// one warp per dst node, lane = feature. Gather-only conv:
// u_out[n,f] = 0.9 * invdeg[n] * sum_{src in N(n)} u_in[src,f] + 0.1 * u0[n,f]
__global__ void __launch_bounds__(256) k_conv(int in_sel, int out_sel) {
    const float* __restrict__ u_in = buf(in_sel);
    float* __restrict__ u_out = buf(out_sel);

    __shared__ int sidx[8][32];
    int gwarp = (blockIdx.x * blockDim.x + threadIdx.x) >> 5;
    int lane  = threadIdx.x & 31;
    int wslot = (threadIdx.x >> 5);
    if (gwarp >= NN) return;

    int beg = g_rowptr[gwarp];
    int end = g_rowptr[gwarp + 1];

    float acc = 0.0f;
    for (int base = beg; base < end; base += 32) {
        int m = end - base; if (m > 32) m = 32;
        if (lane < m) sidx[wslot][lane] = g_col[base + lane];
        __syncwarp();
        int j = 0;
        for (; j + 4 <= m; j += 4) {
            int s0 = sidx[wslot][j + 0];
            int s1 = sidx[wslot][j + 1];
            int s2 = sidx[wslot][j + 2];
            int s3 = sidx[wslot][j + 3];
            float v0 = __ldg(&u_in[s0 * 32 + lane]);
            float v1 = __ldg(&u_in[s1 * 32 + lane]);
            float v2 = __ldg(&u_in[s2 * 32 + lane]);
            float v3 = __ldg(&u_in[s3 * 32 + lane]);
            acc += v0; acc += v1; acc += v2; acc += v3;
        }
        for (; j < m; j++)
            acc += __ldg(&u_in[sidx[wslot][j] * 32 + lane]);
        __syncwarp();
    }
    int o = gwarp * 32 + lane;
    u_out[o] = DIFF * g_invdeg[gwarp] * acc + (1.0f - DIFF) * g_u0[o];
}

// per-(node,feature) MLP applied elementwise, with rescale in/out of u-space.
// Reads g_ub, writes new u0 (= mlp_out * isd) into g_u0.
__global__ void k_mlp(const float* __restrict__ emb,
                      const float* __restrict__ W1,
                      const float* __restrict__ b1,
                      const float* __restrict__ W2,
                      const float* __restrict__ b2) {
    __shared__ float sA[HID];           // W1 row 0
    __shared__ float sW2[HID];
    __shared__ float sC[FF][HID];       // b1[j] + sum_d emb[f,d]*W1[1+d,j]
    __shared__ float sB2;

    for (int t = threadIdx.x; t < FF * HID; t += blockDim.x) {
        int f = t / HID, j = t % HID;
        float c = b1[j];
        #pragma unroll
        for (int d = 0; d < EMB_DIM; d++)
            c += emb[f * EMB_DIM + d] * W1[(1 + d) * HID + j];
        sC[f][j] = c;
    }
    if (threadIdx.x < HID) {
        sA[threadIdx.x]  = W1[threadIdx.x];      // row 0
        sW2[threadIdx.x] = W2[threadIdx.x];
    }
    if (threadIdx.x == 0) sB2 = b2[0];
    __syncthreads();

    int idx = blockIdx.x * blockDim.x + threadIdx.x;
    if (idx >= NF) return;
    int n = idx >> 5;
    int f = idx & 31;
    float t = g_ub[idx] * g_sqd[n];
    float r = sB2;
    #pragma unroll
    for (int j = 0; j < HID; j++) {
        float h = fmaf(sA[j], t, sC[f][j]);
        r = fmaf(sW2[j], fmaxf(h, 0.0f), r);
    }
    g_u0[idx] = r * g_isd[n];
}

// out[n,c] = bout[c] + sum_k (g_ub[n,k]*sqd[n]) * Wout[k,c]
__global__ void k_out(const float* __restrict__ Wout,
                      const float* __restrict__ bout,
                      float* __restrict__ out) {
    __shared__ float sW[FF * CC];
    __shared__ float sb[CC];
    for (int t = threadIdx.x; t < FF * CC; t += blockDim.x) sW[t] = Wout[t];
    if (threadIdx.x < CC) sb[threadIdx.x] = bout[threadIdx.x];
    __syncthreads();

    int tid = blockIdx.x * blockDim.x + threadIdx.x;
    if (tid >= NN * CC) return;
    int n = tid >> 4;
    int c = tid & 15;
    float sd = g_sqd[n];
    float acc = sb[c];
    #pragma unroll
    for (int k = 0; k < FF; k++)
        acc = fmaf(g_ub[n * 32 + k] * sd, sW[k * CC + c], acc);
    out[tid] = acc;
}

// ---------------- launch ----------------

extern "C" void kernel_launch(void* const* d_in, const int* in_sizes, int n_in,
                              void* d_out, int out_size) {
    const float* x     = (const float*)d_in[0];
    const int*   edges = (const int*)d_in[1];       // int32 per harness dtype contract
    const float* emb   = (const float*)d_in[2];
    const float* W1    = (const float*)d_in[3];
    const float* b1    = (const float*)d_in[4];
    const float* W2    = (const float*)d_in[5];
    const float* b2    = (const float*)d_in[6];
    const float* Wout  = (const float*)d_in[7];
    const float* bout  = (const float*)d_in[8];
    float* out = (float*)d_out;

    const int TB = 256;
    int gN  = (NN + TB - 1) / TB;
    int gE  = (EE + TB - 1) / TB;
    int gNF = (NF + TB - 1) / TB;
    int gNC = (NN * CC + TB - 1) / TB;

    // CSR build + scalars
    k_zero<<<gN, TB>>>();
    k_count<<<gE, TB>>>(edges);
    k_scan<<<1, 1024>>>();
    k_prep<<<gNF, TB>>>(x);
    k_fill<<<gE, TB>>>(edges);

    // diffuse 1: u starts at u0 (sel 0); 10 conv steps ping-pong ua(1)/ub(2) -> ends in ub
    k_conv<<<gNF, TB>>>(0, 1);
    for (int i = 1; i < DEPTH; i++) {
        int in_sel  = (i & 1) ? 1 : 2;
        int out_sel = (i & 1) ? 2 : 1;
        k_conv<<<gNF, TB>>>(in_sel, out_sel);
    }

    // per-element MLP (reads g_ub, writes new u0)
    k_mlp<<<gNF, TB>>>(emb, W1, b1, W2, b2);

    // diffuse 2
    k_conv<<<gNF, TB>>>(0, 1);
    for (int i = 1; i < DEPTH; i++) {
        int in_sel  = (i & 1) ? 1 : 2;
        int out_sel = (i & 1) ? 2 : 1;
        k_conv<<<gNF, TB>>>(in_sel, out_sel);
    }

    // output GEMM
    k_out<<<gNC, TB>>>(Wout, bout, out);
}

// round 4
// speedup vs baseline: 1.6270x; 1.6270x over previous
#include <cuda_runtime.h>
#include <cuda_bf16.h>

// Problem constants (fixed by the reference)
#define NN      100000      // nodes
#define FF      32          // feats
#define CC      16          // classes
#define EE      1600000     // edges
#define EMB_DIM 6
#define HID     9
#define DEPTH   10
#define DIFF    0.9f
#define ODIFF   0.1f        // 1 - DIFF

#define NF  (NN * FF)
#define NF4 (NF / 4)        // float4 elements per u buffer

// ---------------- device scratch (no allocs allowed) ----------------
__device__ int    g_cnt[NN];
__device__ int    g_cur[NN];
__device__ int    g_rowptr[NN + 1];
__device__ int    g_col[EE];
__device__ float  g_invdeg[NN];
__device__ float  g_isd[NN];   // rsqrt(max(deg,1))
__device__ float  g_sqd[NN];   // sqrt(max(deg,1))
__device__ float4 g_u0v[NF4];  // declared float4 => 16B aligned
__device__ float4 g_uav[NF4];
__device__ float4 g_ubv[NF4];

__device__ __forceinline__ float4* bufv(int sel) {
    return (sel == 0) ? g_u0v : (sel == 1) ? g_uav : g_ubv;
}

// ---------------- kernels ----------------

__global__ void k_zero() {
    int i = blockIdx.x * blockDim.x + threadIdx.x;
    if (i < NN) { g_cnt[i] = 0; g_cur[i] = 0; }
}

__global__ void k_count(const int* __restrict__ edges) {
    int e = blockIdx.x * blockDim.x + threadIdx.x;
    if (e < EE) {
        int d = edges[EE + e];
        if ((unsigned)d < (unsigned)NN)
            atomicAdd(&g_cnt[d], 1);
    }
}

// single-block exclusive scan of g_cnt -> g_rowptr (N=100000, 1024 threads)
__global__ void k_scan() {
    const int T = 1024;
    int tid = threadIdx.x;
    int chunk = (NN + T - 1) / T;                 // 98
    int beg = tid * chunk;
    int end = beg + chunk; if (end > NN) end = NN;
    if (beg > NN) beg = NN;

    int sum = 0;
    for (int i = beg; i < end; i++) sum += g_cnt[i];

    __shared__ int sh[T];
    sh[tid] = sum;
    __syncthreads();
    for (int off = 1; off < T; off <<= 1) {
        int v = (tid >= off) ? sh[tid - off] : 0;
        __syncthreads();
        sh[tid] += v;
        __syncthreads();
    }
    int run = (tid == 0) ? 0 : sh[tid - 1];       // exclusive prefix
    for (int i = beg; i < end; i++) {
        g_rowptr[i] = run;
        run += g_cnt[i];
    }
    if (tid == T - 1) g_rowptr[NN] = run;         // == EE
}

// per-node scalars + u0 = x * rsqrt(deg)
__global__ void k_prep(const float* __restrict__ x) {
    int idx = blockIdx.x * blockDim.x + threadIdx.x;
    if (idx >= NF) return;
    int n = idx >> 5;
    int c = g_cnt[n];
    float d   = (c > 0) ? (float)c : 1.0f;
    float isd = rsqrtf(d);
    ((float*)g_u0v)[idx] = x[idx] * isd;
    if ((idx & 31) == 0) {
        g_invdeg[n] = 1.0f / d;
        g_isd[n]    = isd;
        g_sqd[n]    = sqrtf(d);
    }
}

__global__ void k_fill(const int* __restrict__ edges) {
    int e = blockIdx.x * blockDim.x + threadIdx.x;
    if (e < EE) {
        int s = edges[e];
        int d = edges[EE + e];
        if ((unsigned)d < (unsigned)NN && (unsigned)s < (unsigned)NN) {
            int pos = g_rowptr[d] + atomicAdd(&g_cur[d], 1);
            g_col[pos] = s;
        }
    }
}

// one warp per dst node; 4 groups of 8 lanes; group g gathers neighbor j+g
// as 8x float4 (full 128B row per group). Butterfly-combine groups at end.
// u_out[n,:] = 0.9 * invdeg[n] * sum_{s in N(n)} u_in[s,:] + 0.1 * u0[n,:]
__global__ void __launch_bounds__(256) k_conv(int in_sel, int out_sel) {
    const float4* __restrict__ u_in  = bufv(in_sel);
    float4* __restrict__       u_out = bufv(out_sel);

    int gwarp = (blockIdx.x * blockDim.x + threadIdx.x) >> 5;
    if (gwarp >= NN) return;
    int lane = threadIdx.x & 31;
    int sub  = lane >> 3;      // neighbor group 0..3
    int fl   = lane & 7;       // float4 slot within row 0..7

    int beg = g_rowptr[gwarp];
    int end = g_rowptr[gwarp + 1];

    float4 acc = make_float4(0.f, 0.f, 0.f, 0.f);
    int j = beg + sub;
    // main: 16 neighbors per iteration (4 per group), 4 independent LDG.128/lane
    for (; j + 12 < end; j += 16) {
        int s0 = __ldg(&g_col[j]);
        int s1 = __ldg(&g_col[j + 4]);
        int s2 = __ldg(&g_col[j + 8]);
        int s3 = __ldg(&g_col[j + 12]);
        float4 v0 = __ldg(&u_in[s0 * 8 + fl]);
        float4 v1 = __ldg(&u_in[s1 * 8 + fl]);
        float4 v2 = __ldg(&u_in[s2 * 8 + fl]);
        float4 v3 = __ldg(&u_in[s3 * 8 + fl]);
        acc.x += v0.x + v1.x + v2.x + v3.x;
        acc.y += v0.y + v1.y + v2.y + v3.y;
        acc.z += v0.z + v1.z + v2.z + v3.z;
        acc.w += v0.w + v1.w + v2.w + v3.w;
    }
    // tail: each group advances by 4, self-predicated
    for (; j < end; j += 4) {
        int s = __ldg(&g_col[j]);
        float4 v = __ldg(&u_in[s * 8 + fl]);
        acc.x += v.x; acc.y += v.y; acc.z += v.z; acc.w += v.w;
    }

    // combine the 4 group partials (lanes with equal fl across groups)
    #pragma unroll
    for (int off = 8; off < 32; off <<= 1) {
        acc.x += __shfl_xor_sync(0xffffffffu, acc.x, off);
        acc.y += __shfl_xor_sync(0xffffffffu, acc.y, off);
        acc.z += __shfl_xor_sync(0xffffffffu, acc.z, off);
        acc.w += __shfl_xor_sync(0xffffffffu, acc.w, off);
    }

    if (sub == 0) {
        float  w  = DIFF * g_invdeg[gwarp];
        float4 h0 = __ldg(&g_u0v[gwarp * 8 + fl]);
        float4 r;
        r.x = fmaf(w, acc.x, ODIFF * h0.x);
        r.y = fmaf(w, acc.y, ODIFF * h0.y);
        r.z = fmaf(w, acc.z, ODIFF * h0.z);
        r.w = fmaf(w, acc.w, ODIFF * h0.w);
        u_out[gwarp * 8 + fl] = r;
    }
}

// per-(node,feature) MLP applied elementwise, with rescale in/out of u-space.
// Reads g_ub, writes new u0 (= mlp_out * isd) into g_u0.
__global__ void k_mlp(const float* __restrict__ emb,
                      const float* __restrict__ W1,
                      const float* __restrict__ b1,
                      const float* __restrict__ W2,
                      const float* __restrict__ b2) {
    __shared__ float sA[HID];           // W1 row 0
    __shared__ float sW2[HID];
    __shared__ float sC[FF][HID];       // b1[j] + sum_d emb[f,d]*W1[1+d,j]
    __shared__ float sB2;

    for (int t = threadIdx.x; t < FF * HID; t += blockDim.x) {
        int f = t / HID, j = t % HID;
        float c = b1[j];
        #pragma unroll
        for (int d = 0; d < EMB_DIM; d++)
            c += emb[f * EMB_DIM + d] * W1[(1 + d) * HID + j];
        sC[f][j] = c;
    }
    if (threadIdx.x < HID) {
        sA[threadIdx.x]  = W1[threadIdx.x];      // row 0
        sW2[threadIdx.x] = W2[threadIdx.x];
    }
    if (threadIdx.x == 0) sB2 = b2[0];
    __syncthreads();

    int idx = blockIdx.x * blockDim.x + threadIdx.x;
    if (idx >= NF) return;
    int n = idx >> 5;
    int f = idx & 31;
    float t = ((const float*)g_ubv)[idx] * g_sqd[n];
    float r = sB2;
    #pragma unroll
    for (int j = 0; j < HID; j++) {
        float h = fmaf(sA[j], t, sC[f][j]);
        r = fmaf(sW2[j], fmaxf(h, 0.0f), r);
    }
    ((float*)g_u0v)[idx] = r * g_isd[n];
}

// out[n,c] = bout[c] + sum_k (ub[n,k]*sqd[n]) * Wout[k,c]
__global__ void k_out(const float* __restrict__ Wout,
                      const float* __restrict__ bout,
                      float* __restrict__ out) {
    __shared__ float sW[FF * CC];
    __shared__ float sb[CC];
    for (int t = threadIdx.x; t < FF * CC; t += blockDim.x) sW[t] = Wout[t];
    if (threadIdx.x < CC) sb[threadIdx.x] = bout[threadIdx.x];
    __syncthreads();

    int tid = blockIdx.x * blockDim.x + threadIdx.x;
    if (tid >= NN * CC) return;
    int n = tid >> 4;
    int c = tid & 15;
    float sd = g_sqd[n];
    const float* u = (const float*)g_ubv;
    float acc = sb[c];
    #pragma unroll
    for (int k = 0; k < FF; k++)
        acc = fmaf(u[n * 32 + k] * sd, sW[k * CC + c], acc);
    out[tid] = acc;
}

// ---------------- launch ----------------

extern "C" void kernel_launch(void* const* d_in, const int* in_sizes, int n_in,
                              void* d_out, int out_size) {
    const float* x     = (const float*)d_in[0];
    const int*   edges = (const int*)d_in[1];       // int32 per harness dtype contract
    const float* emb   = (const float*)d_in[2];
    const float* W1    = (const float*)d_in[3];
    const float* b1    = (const float*)d_in[4];
    const float* W2    = (const float*)d_in[5];
    const float* b2    = (const float*)d_in[6];
    const float* Wout  = (const float*)d_in[7];
    const float* bout  = (const float*)d_in[8];
    float* out = (float*)d_out;

    const int TB = 256;
    int gN  = (NN + TB - 1) / TB;
    int gE  = (EE + TB - 1) / TB;
    int gNF = (NF + TB - 1) / TB;
    int gW  = (NN * 32 + TB - 1) / TB;   // warp-per-node grid
    int gNC = (NN * CC + TB - 1) / TB;

    // CSR build + scalars
    k_zero<<<gN, TB>>>();
    k_count<<<gE, TB>>>(edges);
    k_scan<<<1, 1024>>>();
    k_prep<<<gNF, TB>>>(x);
    k_fill<<<gE, TB>>>(edges);

    // diffuse 1: u starts at u0 (sel 0); 10 conv steps ping-pong ua(1)/ub(2) -> ends in ub
    k_conv<<<gW, TB>>>(0, 1);
    for (int i = 1; i < DEPTH; i++) {
        int in_sel  = (i & 1) ? 1 : 2;
        int out_sel = (i & 1) ? 2 : 1;
        k_conv<<<gW, TB>>>(in_sel, out_sel);
    }

    // per-element MLP (reads g_ub, writes new u0)
    k_mlp<<<gNF, TB>>>(emb, W1, b1, W2, b2);

    // diffuse 2
    k_conv<<<gW, TB>>>(0, 1);
    for (int i = 1; i < DEPTH; i++) {
        int in_sel  = (i & 1) ? 1 : 2;
        int out_sel = (i & 1) ? 2 : 1;
        k_conv<<<gW, TB>>>(in_sel, out_sel);
    }

    // output GEMM
    k_out<<<gNC, TB>>>(Wout, bout, out);
}